// round 14
// baseline (speedup 1.0000x reference)
#include <cuda_runtime.h>
#include <math.h>

#define KK   8
#define H    250
#define HP   252
#define NP   56
#define HA_  100
#define MM   576
#define NB   2048
#define BK   (NB*KK)
#define CIN  1076
#define EPS_ 1e-5f
#define K2E  125
#define K2C  250
#define KP   1080
#define NPAD2 256

typedef unsigned long long u64t;

__device__ __forceinline__ u64t pack2(float lo, float hi) {
    u64t r;
    asm("mov.b64 %0, {%1, %2};" : "=l"(r) : "f"(lo), "f"(hi));
    return r;
}
__device__ __forceinline__ void fma2(u64t& d, u64t a, u64t b) {
    asm("fma.rn.f32x2 %0, %1, %2, %0;" : "+l"(d) : "l"(a), "l"(b));
}
__device__ __forceinline__ float sum2(u64t v) {
    float lo, hi;
    asm("mov.b64 {%0, %1}, %2;" : "=f"(lo), "=f"(hi) : "l"(v));
    return lo + hi;
}
__device__ __forceinline__ float tf32r(float f) {
    unsigned u;
    asm("cvt.rna.tf32.f32 %0, %1;" : "=r"(u) : "f"(f));
    return __uint_as_float(u);
}

#define MMA_TF32(D, A, B0, B1) \
    asm volatile("mma.sync.aligned.m16n8k8.row.col.f32.tf32.tf32.f32 " \
        "{%0,%1,%2,%3}, {%4,%5,%6,%7}, {%8,%9}, {%0,%1,%2,%3};" \
        : "+f"((D)[0]), "+f"((D)[1]), "+f"((D)[2]), "+f"((D)[3]) \
        : "r"((A)[0]), "r"((A)[1]), "r"((A)[2]), "r"((A)[3]), "r"(B0), "r"(B1))

// scratch + packed weights (allocation-free rule: device globals)
__device__ float g_s1 [(size_t)BK * H];
__device__ float g_eff[(size_t)BK * H];
__device__ u64t  g_Wenc [K2E * H];
__device__ u64t  g_Wcore[K2C * H];
__device__ u64t  g_Wctx [K2E * H];      // pre-multiplied by core_g (LN fold)
__device__ u64t  g_Watt [K2E * HA_];    // pre-multiplied by core_g (LN fold)
__device__ float g_t1c[H],  g_t2c[H];
__device__ float g_t1a[HA_], g_t2a[HA_];
// mma path buffers (hi/lo tf32 planes)
__device__ float g_totH[(size_t)BK * KP];
__device__ float g_totL[(size_t)BK * KP];
__device__ float g_WHp [KP * NPAD2];
__device__ float g_WLp [KP * NPAD2];

// ---------------------------------------------------------------------------
// pack kernel
// ---------------------------------------------------------------------------
#define N_E (K2E*H)
#define N_C (K2C*H)
#define N_A (K2E*HA_)
#define N_TOT (N_E + N_C + N_E + N_A)
__global__ void pack_all(const float* __restrict__ encW, const float* __restrict__ coreW,
                         const float* __restrict__ ctxW, const float* __restrict__ attW,
                         const float* __restrict__ core_g) {
    int i = blockIdx.x * 256 + threadIdx.x;
    if (i < N_E) {
        int k2 = i / H, c = i - k2 * H;
        g_Wenc[i] = pack2(encW[(2 * k2) * H + c], encW[(2 * k2 + 1) * H + c]);
        return;
    }
    i -= N_E;
    if (i < N_C) {
        int k2 = i / H, c = i - k2 * H;
        g_Wcore[i] = pack2(coreW[(2 * k2) * H + c], coreW[(2 * k2 + 1) * H + c]);
        return;
    }
    i -= N_C;
    if (i < N_E) {
        int k2 = i / H, c = i - k2 * H;
        g_Wctx[i] = pack2(core_g[2 * k2]     * ctxW[(2 * k2) * H + c],
                          core_g[2 * k2 + 1] * ctxW[(2 * k2 + 1) * H + c]);
        return;
    }
    i -= N_E;
    if (i < N_A) {
        int k2 = i / HA_, c = i - k2 * HA_;
        g_Watt[i] = pack2(core_g[2 * k2]     * attW[(2 * k2) * HA_ + c],
                          core_g[2 * k2 + 1] * attW[(2 * k2 + 1) * HA_ + c]);
    }
}

// ---------------------------------------------------------------------------
// t-vector kernel
// ---------------------------------------------------------------------------
__global__ void tvec_kernel(const float* __restrict__ ctxW, const float* __restrict__ ctx_b,
                            const float* __restrict__ attW, const float* __restrict__ att_b1,
                            const float* __restrict__ core_g, const float* __restrict__ core_bt) {
    int n = blockIdx.x * 256 + threadIdx.x;
    if (n < H) {
        float t1 = 0.f, t2 = 0.f;
        #pragma unroll 4
        for (int c = 0; c < H; c++) {
            float w = ctxW[(size_t)c * H + n];
            t1 += w * core_bt[c];
            t2 += w * core_g[c];
        }
        g_t1c[n] = t1 + ctx_b[n];
        g_t2c[n] = t2;
    } else if (n < H + HA_) {
        int m = n - H;
        float t1 = 0.f, t2 = 0.f;
        #pragma unroll 4
        for (int c = 0; c < H; c++) {
            float w = attW[(size_t)c * HA_ + m];
            t1 += w * core_bt[c];
            t2 += w * core_g[c];
        }
        g_t1a[m] = t1 + att_b1[m];
        g_t2a[m] = t2;
    }
}

// ---------------------------------------------------------------------------
// out_W pad + tf32 hi/lo split
// ---------------------------------------------------------------------------
__global__ void wpad_kernel(const float* __restrict__ W) {
    int i = blockIdx.x * 256 + threadIdx.x;
    if (i >= KP * NPAD2) return;
    int k = i / NPAD2, n = i - k * NPAD2;
    float v = (k < CIN && n < H) ? W[(size_t)k * H + n] : 0.f;
    float hi = tf32r(v);
    g_WHp[i] = hi;
    g_WLp[i] = tf32r(v - hi);
}

// ---------------------------------------------------------------------------
// concat: tf32 hi/lo planes of [s1 | eff | x | 0]
// ---------------------------------------------------------------------------
__global__ void concat_kernel(const float* __restrict__ x) {
    size_t i = (size_t)blockIdx.x * 256 + threadIdx.x;
    if (i >= (size_t)BK * (KP / 4)) return;
    size_t row = i / (KP / 4);
    int k0 = (int)(i % (KP / 4)) * 4;
    float hv[4], lv[4];
    #pragma unroll
    for (int j = 0; j < 4; j++) {
        int k = k0 + j;
        float v;
        if (k < H)            v = g_s1[row * H + k];
        else if (k < 2 * H)   v = g_eff[row * H + (k - H)];
        else if (k < CIN)     v = x[row * MM + (k - 2 * H)];
        else                  v = 0.f;
        float hi = tf32r(v);
        hv[j] = hi;
        lv[j] = tf32r(v - hi);
    }
    *(float4*)&g_totH[row * KP + k0] = make_float4(hv[0], hv[1], hv[2], hv[3]);
    *(float4*)&g_totL[row * KP + k0] = make_float4(lv[0], lv[1], lv[2], lv[3]);
}

// ---------------------------------------------------------------------------
// shared FFMA2 GEMM helpers
// ---------------------------------------------------------------------------
template<int NR>
__device__ __forceinline__ void chunk_body(
    u64t* a0, u64t* a1, const float* base, int rowstride, int k,
    const u64t* wa0, const u64t* wa1)
{
    #pragma unroll
    for (int e = 0; e < NR; e++) {
        ulonglong2 v0 = *(const ulonglong2*)&base[e * rowstride + k];
        ulonglong2 v1 = *(const ulonglong2*)&base[e * rowstride + k + 4];
        fma2(a0[e], v0.x, wa0[0]); fma2(a0[e], v0.y, wa0[1]);
        fma2(a0[e], v1.x, wa0[2]); fma2(a0[e], v1.y, wa0[3]);
        fma2(a1[e], v0.x, wa1[0]); fma2(a1[e], v0.y, wa1[1]);
        fma2(a1[e], v1.x, wa1[2]); fma2(a1[e], v1.y, wa1[3]);
    }
}
__device__ __forceinline__ void ldw4(u64t* w0, u64t* w1,
                                     const u64t* W0, const u64t* W1,
                                     int k2, int stride) {
    #pragma unroll
    for (int j = 0; j < 4; j++) {
        w0[j] = W0[(size_t)(k2 + j) * stride];
        w1[j] = W1[(size_t)(k2 + j) * stride];
    }
}
__device__ __forceinline__ void cpw4(u64t* wa0, u64t* wa1,
                                     const u64t* wb0, const u64t* wb1) {
    #pragma unroll
    for (int j = 0; j < 4; j++) { wa0[j] = wb0[j]; wa1[j] = wb1[j]; }
}

// ---------------------------------------------------------------------------
// Kernel 1: s1 = LN(relu(state @ enc_W + enc_b)); (unchanged)
// ---------------------------------------------------------------------------
#define ER 16
__global__ __launch_bounds__(256, 2) void enc_kernel(
    const float* __restrict__ state, const float* __restrict__ b,
    const float* __restrict__ g, const float* __restrict__ bt)
{
    __shared__ float sst[ER * HP];
    __shared__ float st[ER * 2];

    const int t = threadIdx.x;
    const size_t base = (size_t)blockIdx.x * ER;
    const float* srow = state + base * H;

    for (int i = t; i < ER * H; i += 256) {
        int r = i / H, c = i - r * H;
        sst[r * HP + c] = srow[i];
    }
    __syncthreads();

    const int h = t >> 7, u = t & 127;
    const int c0 = u, c1 = u + 128;
    const int c1ok = (c1 < H);
    const int c1v = c1ok ? c1 : 0;

    float relu0[8], relu1[8];
    {
        const u64t* W0 = g_Wenc + c0;
        const u64t* W1 = g_Wenc + c1v;
        const float* sr = sst + h * 8 * HP;
        u64t a0[8], a1[8];
        #pragma unroll
        for (int e = 0; e < 8; e++) { a0[e] = 0ull; a1[e] = 0ull; }

        u64t wa0[4], wa1[4];
        ldw4(wa0, wa1, W0, W1, 0, H);
        #pragma unroll 2
        for (int kc = 0; kc < 120; kc += 4) {
            u64t wb0[4], wb1[4];
            ldw4(wb0, wb1, W0, W1, kc + 4, H);
            chunk_body<8>(a0, a1, sr, HP, 2 * kc, wa0, wa1);
            cpw4(wa0, wa1, wb0, wb1);
        }
        chunk_body<8>(a0, a1, sr, HP, 240, wa0, wa1);
        {
            u64t wt0 = W0[(size_t)124 * H], wt1 = W1[(size_t)124 * H];
            #pragma unroll
            for (int e = 0; e < 8; e++) {
                u64t v = *(const u64t*)&sr[e * HP + 248];
                fma2(a0[e], v, wt0);
                fma2(a1[e], v, wt1);
            }
        }
        float b0 = b[c0], b1 = b[c1v];
        #pragma unroll
        for (int e = 0; e < 8; e++) {
            relu0[e] = fmaxf(sum2(a0[e]) + b0, 0.f);
            relu1[e] = fmaxf(sum2(a1[e]) + b1, 0.f);
        }
    }
    __syncthreads();
    #pragma unroll
    for (int e = 0; e < 8; e++) {
        sst[(8 * h + e) * HP + c0] = relu0[e];
        if (c1ok) sst[(8 * h + e) * HP + c1] = relu1[e];
    }
    __syncthreads();

    const int warp = t >> 5, lane = t & 31;
    for (int r = warp; r < ER; r += 8) {
        float s = 0.f, s2 = 0.f;
        for (int k = lane; k < H; k += 32) {
            float v = sst[r * HP + k];
            s += v; s2 += v * v;
        }
        #pragma unroll
        for (int off = 16; off; off >>= 1) {
            s  += __shfl_xor_sync(0xffffffffu, s,  off);
            s2 += __shfl_xor_sync(0xffffffffu, s2, off);
        }
        if (lane == 0) {
            float mu = s * (1.f / H);
            st[r * 2]     = mu;
            st[r * 2 + 1] = rsqrtf(s2 * (1.f / H) - mu * mu + EPS_);
        }
    }
    __syncthreads();

    {
        float g0 = g[c0], bb0 = bt[c0];
        float g1 = g[c1v], bb1 = bt[c1v];
        #pragma unroll
        for (int e = 0; e < 8; e++) {
            int r = 8 * h + e;
            g_s1[(base + r) * H + c0] = (relu0[e] - st[r * 2]) * st[r * 2 + 1] * g0 + bb0;
            if (c1ok)
                g_s1[(base + r) * H + c1] = (relu1[e] - st[r * 2]) * st[r * 2 + 1] * g1 + bb1;
        }
    }
}

// ---------------------------------------------------------------------------
// Kernel 2: fused pair pipeline; staged SMEM weights for ctx/att1,
// distance-2 register prefetch in core.
// ---------------------------------------------------------------------------
__global__ __launch_bounds__(512, 1) void pair_kernel(
    const float* __restrict__ core_b,
    const float* __restrict__ ctx_g,  const float* __restrict__ ctx_bt,
    const float* __restrict__ att_g,  const float* __restrict__ att_bt,
    const float* __restrict__ att_W2, const float* __restrict__ att_b2)
{
    extern __shared__ float sm[];
    float* s1s   = sm;                    // 8  * HP
    float* fbufA = s1s   + KK * HP;       // 4 partial buffers (32KB), later = wstage
    float* fbufB = fbufA + KK * HP;
    float* obufA = fbufB + KK * HP;
    float* obufB = obufA + KK * HP;
    float* coreb = obufB + KK * HP;       // 56 * HP (raw, post-relu)
    float* ctxb  = coreb + NP * HP;       // 56 * HP (raw, post-relu)
    float* attb  = ctxb  + NP * HP;       // 56 * HA_
    float* attv  = attb  + NP * HA_;      // 56
    float* stA   = attv  + NP;            // 56*2  (mu*rs, rs) of coreb
    float* stC   = stA   + NP * 2;        // 56*2  (mu*rs, rs) of ctxb
    u64t*  wstage = (u64t*)fbufA;         // staged weights (2 x 2000 u64 max)

    const int t = threadIdx.x;
    const int grp = blockIdx.x;
    const int warp = t >> 5, lane = t & 31;

    const int qg = t >> 7, u = t & 127;
    const int c0 = u, c1 = u + 128;
    const int c1ok = (c1 < H);
    const int c1v = c1ok ? c1 : 0;

    for (int i = t; i < KK * H; i += 512) {
        int r = i / H, c = i - r * H;
        s1s[r * HP + c] = g_s1[((size_t)grp * KK + r) * H + c];
    }
    __syncthreads();

    // ---- core GEMM: quadrant = (k-half, focal/other); distance-2 prefetch --
    {
        const int wh = qg & 1;
        const int kh = qg >> 1;
        const u64t* W0 = g_Wcore + (size_t)(wh * 125) * H + c0;
        const u64t* W1 = g_Wcore + (size_t)(wh * 125) * H + c1v;
        u64t a0[8], a1[8];
        #pragma unroll
        for (int e = 0; e < 8; e++) { a0[e] = 0ull; a1[e] = 0ull; }

        const int kcs = kh ? 64 : 0;
        const int niter = kh ? 15 : 16;
        u64t wa0[4], wa1[4], wb0[4], wb1[4];
        u64t wc0[4] = {0,0,0,0}, wc1[4] = {0,0,0,0};
        ldw4(wa0, wa1, W0, W1, kcs, H);
        ldw4(wb0, wb1, W0, W1, kcs + 4, H);
        #pragma unroll 1
        for (int i = 0; i < niter; i++) {
            if (i + 2 < niter) ldw4(wc0, wc1, W0, W1, kcs + 4 * (i + 2), H);
            chunk_body<8>(a0, a1, s1s, HP, 2 * (kcs + 4 * i), wa0, wa1);
            cpw4(wa0, wa1, wb0, wb1);
            cpw4(wb0, wb1, wc0, wc1);
        }
        if (kh) {   // tail k2 = 124 (k = 248,249)
            u64t wt0 = W0[(size_t)124 * H], wt1 = W1[(size_t)124 * H];
            #pragma unroll
            for (int e = 0; e < 8; e++) {
                u64t v = *(const u64t*)&s1s[e * HP + 248];
                fma2(a0[e], v, wt0);
                fma2(a1[e], v, wt1);
            }
        }
        float* fd = kh ? (wh ? obufB : fbufB) : (wh ? obufA : fbufA);
        #pragma unroll
        for (int e = 0; e < 8; e++) {
            fd[e * HP + c0] = sum2(a0[e]);
            if (c1ok) fd[e * HP + c1] = sum2(a1[e]);
        }
    }
    __syncthreads();

    // ---- merged assemble + LN stats (warp per pair; division-free) ----
    for (int p = warp; p < NP; p += 16) {
        const int fi = (p * 9363) >> 16;        // p / 7
        const int jj = p - fi * 7;
        const int o = jj + (jj >= fi);
        const float* fA = fbufA + fi * HP;
        const float* fB = fbufB + fi * HP;
        const float* oA = obufA + o * HP;
        const float* oB = obufB + o * HP;
        float s = 0.f, s2 = 0.f;
        for (int c = lane; c < H; c += 32) {
            float v = fmaxf(fA[c] + fB[c] + oA[c] + oB[c] + core_b[c], 0.f);
            coreb[p * HP + c] = v;
            s += v; s2 += v * v;
        }
        #pragma unroll
        for (int off = 16; off; off >>= 1) {
            s  += __shfl_xor_sync(0xffffffffu, s,  off);
            s2 += __shfl_xor_sync(0xffffffffu, s2, off);
        }
        if (lane == 0) {
            float mu = s * (1.f / H);
            float rs = rsqrtf(s2 * (1.f / H) - mu * mu + EPS_);
            stA[2 * p]     = mu * rs;
            stA[2 * p + 1] = rs;
        }
    }
    __syncthreads();     // partial buffers now dead -> become wstage

    // ---- ctx GEMM: staged SMEM weights, double-buffered, 16 slices x 8 k2 --
    {
        const int pbase = qg * 14;
        u64t a0[14], a1[14];
        #pragma unroll
        for (int pp = 0; pp < 14; pp++) { a0[pp] = 0ull; a1[pp] = 0ull; }

        // preload slice 0
        #pragma unroll
        for (int j = 0; j < 4; j++) {
            int e = t + 512 * j;
            if (e < 2000) wstage[e] = g_Wctx[e];
        }
        __syncthreads();

        int buf = 0;
        #pragma unroll 1
        for (int s = 0; s < 16; s++) {
            // prefetch next slice into regs (latency covered by compute below)
            u64t r[4];
            if (s < 15) {
                const int nbase = (s + 1) * 2000;
                const int ncnt = (s == 14) ? 1250 : 2000;
                #pragma unroll
                for (int j = 0; j < 4; j++) {
                    int e = t + 512 * j;
                    r[j] = (e < ncnt) ? g_Wctx[nbase + e] : 0;
                }
            }
            const u64t* wb = wstage + buf * 2000;
            const int k2s = s * 8;
            if (s < 15) {
                #pragma unroll
                for (int j = 0; j < 8; j += 2) {
                    u64t w00 = wb[j * 250 + c0];
                    u64t w01 = wb[j * 250 + 250 + c0];
                    u64t w10 = wb[j * 250 + c1v];
                    u64t w11 = wb[j * 250 + 250 + c1v];
                    const int k = 2 * (k2s + j);
                    #pragma unroll
                    for (int pp = 0; pp < 14; pp++) {
                        ulonglong2 v = *(const ulonglong2*)&coreb[(pbase + pp) * HP + k];
                        fma2(a0[pp], v.x, w00); fma2(a0[pp], v.y, w01);
                        fma2(a1[pp], v.x, w10); fma2(a1[pp], v.y, w11);
                    }
                }
            } else {    // k2 120..124
                #pragma unroll
                for (int j = 0; j < 4; j += 2) {
                    u64t w00 = wb[j * 250 + c0];
                    u64t w01 = wb[j * 250 + 250 + c0];
                    u64t w10 = wb[j * 250 + c1v];
                    u64t w11 = wb[j * 250 + 250 + c1v];
                    const int k = 2 * (k2s + j);
                    #pragma unroll
                    for (int pp = 0; pp < 14; pp++) {
                        ulonglong2 v = *(const ulonglong2*)&coreb[(pbase + pp) * HP + k];
                        fma2(a0[pp], v.x, w00); fma2(a0[pp], v.y, w01);
                        fma2(a1[pp], v.x, w10); fma2(a1[pp], v.y, w11);
                    }
                }
                u64t w0 = wb[4 * 250 + c0];
                u64t w1 = wb[4 * 250 + c1v];
                #pragma unroll
                for (int pp = 0; pp < 14; pp++) {
                    u64t v = *(const u64t*)&coreb[(pbase + pp) * HP + 248];
                    fma2(a0[pp], v, w0);
                    fma2(a1[pp], v, w1);
                }
            }
            if (s < 15) {
                u64t* wn = wstage + (buf ^ 1) * 2000;
                #pragma unroll
                for (int j = 0; j < 4; j++) {
                    int e = t + 512 * j;
                    if (e < 2000) wn[e] = r[j];
                }
                __syncthreads();
                buf ^= 1;
            }
        }
        const float t10 = g_t1c[c0], t20 = g_t2c[c0];
        const float t11 = g_t1c[c1v], t21 = g_t2c[c1v];
        #pragma unroll
        for (int pp = 0; pp < 14; pp++) {
            const int p = pbase + pp;
            const float ms = stA[2 * p], rs = stA[2 * p + 1];
            ctxb[p * HP + c0] = fmaxf(rs * sum2(a0[pp]) - ms * t20 + t10, 0.f);
            if (c1ok)
                ctxb[p * HP + c1] = fmaxf(rs * sum2(a1[pp]) - ms * t21 + t11, 0.f);
        }
    }

    // ---- att1 GEMM: staged SMEM weights, 16 slices x 8 k2 ----
    __syncthreads();      // all ctx reads of wstage done before overwrite
    {
        #pragma unroll
        for (int j = 0; j < 2; j++) {
            int e = t + 512 * j;
            if (e < 800) wstage[e] = g_Watt[e];
        }
        __syncthreads();

        const int g8 = t >> 6, u6 = t & 63;
        const int act = (u6 < 50);
        const int pbase = g8 * 7;
        const int ac0 = act ? u6 : 0, ac1 = ac0 + 50;
        u64t a0[7], a1[7];
        #pragma unroll
        for (int pp = 0; pp < 7; pp++) { a0[pp] = 0ull; a1[pp] = 0ull; }

        int buf = 0;
        #pragma unroll 1
        for (int s = 0; s < 16; s++) {
            u64t r[2];
            if (s < 15) {
                const int nbase = (s + 1) * 800;
                const int ncnt = (s == 14) ? 500 : 800;
                #pragma unroll
                for (int j = 0; j < 2; j++) {
                    int e = t + 512 * j;
                    r[j] = (e < ncnt) ? g_Watt[nbase + e] : 0;
                }
            }
            const u64t* wb = wstage + buf * 800;
            const int k2s = s * 8;
            if (act) {
                if (s < 15) {
                    #pragma unroll
                    for (int j = 0; j < 8; j += 2) {
                        u64t w00 = wb[j * 100 + ac0];
                        u64t w01 = wb[j * 100 + 100 + ac0];
                        u64t w10 = wb[j * 100 + ac1];
                        u64t w11 = wb[j * 100 + 100 + ac1];
                        const int k = 2 * (k2s + j);
                        #pragma unroll
                        for (int pp = 0; pp < 7; pp++) {
                            ulonglong2 v = *(const ulonglong2*)&coreb[(pbase + pp) * HP + k];
                            fma2(a0[pp], v.x, w00); fma2(a0[pp], v.y, w01);
                            fma2(a1[pp], v.x, w10); fma2(a1[pp], v.y, w11);
                        }
                    }
                } else {
                    #pragma unroll
                    for (int j = 0; j < 4; j += 2) {
                        u64t w00 = wb[j * 100 + ac0];
                        u64t w01 = wb[j * 100 + 100 + ac0];
                        u64t w10 = wb[j * 100 + ac1];
                        u64t w11 = wb[j * 100 + 100 + ac1];
                        const int k = 2 * (k2s + j);
                        #pragma unroll
                        for (int pp = 0; pp < 7; pp++) {
                            ulonglong2 v = *(const ulonglong2*)&coreb[(pbase + pp) * HP + k];
                            fma2(a0[pp], v.x, w00); fma2(a0[pp], v.y, w01);
                            fma2(a1[pp], v.x, w10); fma2(a1[pp], v.y, w11);
                        }
                    }
                    u64t w0 = wb[4 * 100 + ac0];
                    u64t w1 = wb[4 * 100 + ac1];
                    #pragma unroll
                    for (int pp = 0; pp < 7; pp++) {
                        u64t v = *(const u64t*)&coreb[(pbase + pp) * HP + 248];
                        fma2(a0[pp], v, w0);
                        fma2(a1[pp], v, w1);
                    }
                }
            }
            if (s < 15) {
                u64t* wn = wstage + (buf ^ 1) * 800;
                #pragma unroll
                for (int j = 0; j < 2; j++) {
                    int e = t + 512 * j;
                    if (e < 800) wn[e] = r[j];
                }
                __syncthreads();
                buf ^= 1;
            }
        }
        if (act) {
            const float t10 = g_t1a[ac0], t20 = g_t2a[ac0];
            const float t11 = g_t1a[ac1], t21 = g_t2a[ac1];
            #pragma unroll
            for (int pp = 0; pp < 7; pp++) {
                const int p = pbase + pp;
                const float ms = stA[2 * p], rs = stA[2 * p + 1];
                attb[p * HA_ + ac0] = tanhf(rs * sum2(a0[pp]) - ms * t20 + t10);
                attb[p * HA_ + ac1] = tanhf(rs * sum2(a1[pp]) - ms * t21 + t11);
            }
        }
    }
    __syncthreads();

    // ---- ctx LN stats + att LN + att2 + sigmoid (warp per pair) ----
    for (int p = warp; p < NP; p += 16) {
        {
            float s = 0.f, s2 = 0.f;
            for (int k = lane; k < H; k += 32) {
                float v = ctxb[p * HP + k];
                s += v; s2 += v * v;
            }
            #pragma unroll
            for (int off = 16; off; off >>= 1) {
                s  += __shfl_xor_sync(0xffffffffu, s,  off);
                s2 += __shfl_xor_sync(0xffffffffu, s2, off);
            }
            if (lane == 0) {
                float mu = s * (1.f / H);
                float rs = rsqrtf(s2 * (1.f / H) - mu * mu + EPS_);
                stC[2 * p]     = mu * rs;
                stC[2 * p + 1] = rs;
            }
        }
        {
            float s = 0.f, s2 = 0.f;
            for (int k = lane; k < HA_; k += 32) {
                float v = attb[p * HA_ + k];
                s += v; s2 += v * v;
            }
            #pragma unroll
            for (int off = 16; off; off >>= 1) {
                s  += __shfl_xor_sync(0xffffffffu, s,  off);
                s2 += __shfl_xor_sync(0xffffffffu, s2, off);
            }
            float mu = s * (1.f / HA_);
            float rs = rsqrtf(s2 * (1.f / HA_) - mu * mu + EPS_);
            float s3 = 0.f;
            for (int k = lane; k < HA_; k += 32) {
                float v = (attb[p * HA_ + k] - mu) * rs * att_g[k] + att_bt[k];
                s3 += v * att_W2[k];
            }
            #pragma unroll
            for (int off = 16; off; off >>= 1)
                s3 += __shfl_xor_sync(0xffffffffu, s3, off);
            if (lane == 0)
                attv[p] = 1.f / (1.f + expf(-(s3 + att_b2[0])));
        }
    }
    __syncthreads();

    // ---- effect (folded ctx-LN) ----
    {
        const int c = t & 255, eh = t >> 8;
        if (c < H) {
            const float cgc = ctx_g[c], cbtc = ctx_bt[c];
            #pragma unroll
            for (int e4 = 0; e4 < 4; e4++) {
                const int e = eh * 4 + e4;
                float acc = 0.f, A = 0.f, Bs = 0.f;
                #pragma unroll
                for (int j = 0; j < 7; j++) {
                    const int p = e * 7 + j;
                    const float av = attv[p];
                    const float w  = av * stC[2 * p + 1];
                    acc += w * ctxb[p * HP + c];
                    A   += av;
                    Bs  += av * stC[2 * p];
                }
                g_eff[((size_t)grp * KK + e) * H + c] = cgc * (acc - Bs) + A * cbtc;
            }
        }
    }
}

// ---------------------------------------------------------------------------
// Kernel 3: out GEMM via tf32 mma.sync (3xTF32). (unchanged)
// ---------------------------------------------------------------------------
#define LOAD_STAGE(s, k0) do {                                                        \
    *(float2*)&AsH[s][am * 8 + ak] =                                                  \
        *(const float2*)&g_totH[(size_t)(m0 + am) * KP + (k0) + ak];                  \
    *(float2*)&AsL[s][am * 8 + ak] =                                                  \
        *(const float2*)&g_totL[(size_t)(m0 + am) * KP + (k0) + ak];                  \
    {                                                                                 \
        const float* wh = &g_WHp[(size_t)((k0) + bk) * NPAD2 + bn];                   \
        const float* wl = &g_WLp[(size_t)((k0) + bk) * NPAD2 + bn];                   \
        *(float4*)&BsH[s][bk * 260 + bn]     = *(const float4*)wh;                    \
        *(float4*)&BsH[s][bk * 260 + bn + 4] = *(const float4*)(wh + 4);              \
        *(float4*)&BsL[s][bk * 260 + bn]     = *(const float4*)wl;                    \
        *(float4*)&BsL[s][bk * 260 + bn + 4] = *(const float4*)(wl + 4);              \
    }                                                                                 \
} while (0)

__global__ __launch_bounds__(256, 2) void out_mma_kernel(
    const float* __restrict__ bias, float* __restrict__ out)
{
    __shared__ float AsH[2][64 * 8], AsL[2][64 * 8];
    __shared__ float BsH[2][8 * 260], BsL[2][8 * 260];

    const int t = threadIdx.x;
    const int m0 = blockIdx.x * 64;
    const int w = t >> 5, lane = t & 31;
    const int wm = w & 1, wn = w >> 1;
    const int gid = lane >> 2, ctid = lane & 3;

    const int am = t >> 2;
    const int ak = (t & 3) * 2;
    const int bk = t >> 5;
    const int bn = (t & 31) * 8;

    float d[2][8][4];
    #pragma unroll
    for (int mf = 0; mf < 2; mf++)
        #pragma unroll
        for (int nf = 0; nf < 8; nf++)
            #pragma unroll
            for (int q = 0; q < 4; q++) d[mf][nf][q] = 0.f;

    LOAD_STAGE(0, 0);

    #pragma unroll 1
    for (int ks = 0; ks < 135; ks++) {
        const int s = ks & 1;
        __syncthreads();
        if (ks + 1 < 135) LOAD_STAGE(s ^ 1, (ks + 1) * 8);

        unsigned aH[2][4], aL[2][4];
        #pragma unroll
        for (int mf = 0; mf < 2; mf++) {
            const int rb = wm * 32 + mf * 16;
            aH[mf][0] = __float_as_uint(AsH[s][(rb + gid) * 8 + ctid]);
            aH[mf][1] = __float_as_uint(AsH[s][(rb + gid + 8) * 8 + ctid]);
            aH[mf][2] = __float_as_uint(AsH[s][(rb + gid) * 8 + ctid + 4]);
            aH[mf][3] = __float_as_uint(AsH[s][(rb + gid + 8) * 8 + ctid + 4]);
            aL[mf][0] = __float_as_uint(AsL[s][(rb + gid) * 8 + ctid]);
            aL[mf][1] = __float_as_uint(AsL[s][(rb + gid + 8) * 8 + ctid]);
            aL[mf][2] = __float_as_uint(AsL[s][(rb + gid) * 8 + ctid + 4]);
            aL[mf][3] = __float_as_uint(AsL[s][(rb + gid + 8) * 8 + ctid + 4]);
        }
        #pragma unroll
        for (int nf = 0; nf < 8; nf++) {
            const int n = wn * 64 + nf * 8 + gid;
            unsigned bH0 = __float_as_uint(BsH[s][ctid * 260 + n]);
            unsigned bH1 = __float_as_uint(BsH[s][(ctid + 4) * 260 + n]);
            unsigned bL0 = __float_as_uint(BsL[s][ctid * 260 + n]);
            unsigned bL1 = __float_as_uint(BsL[s][(ctid + 4) * 260 + n]);
            #pragma unroll
            for (int mf = 0; mf < 2; mf++) {
                MMA_TF32(d[mf][nf], aH[mf], bH0, bH1);
                MMA_TF32(d[mf][nf], aL[mf], bH0, bH1);
                MMA_TF32(d[mf][nf], aH[mf], bL0, bL1);
            }
        }
    }

    #pragma unroll
    for (int mf = 0; mf < 2; mf++) {
        const int r0 = m0 + wm * 32 + mf * 16 + gid;
        #pragma unroll
        for (int nf = 0; nf < 8; nf++) {
            const int n = wn * 64 + nf * 8 + 2 * ctid;
            if (n < H) {
                float b0 = bias[n], b1 = bias[n + 1];
                out[(size_t)r0 * H + n]           = d[mf][nf][0] + b0;
                out[(size_t)r0 * H + n + 1]       = d[mf][nf][1] + b1;
                out[(size_t)(r0 + 8) * H + n]     = d[mf][nf][2] + b0;
                out[(size_t)(r0 + 8) * H + n + 1] = d[mf][nf][3] + b1;
            }
        }
    }
}

// ---------------------------------------------------------------------------
extern "C" void kernel_launch(void* const* d_in, const int* in_sizes, int n_in,
                              void* d_out, int out_size)
{
    const float* x       = (const float*)d_in[0];
    const float* state   = (const float*)d_in[1];
    const float* enc_W   = (const float*)d_in[2];
    const float* enc_b   = (const float*)d_in[3];
    const float* enc_g   = (const float*)d_in[4];
    const float* enc_bt  = (const float*)d_in[5];
    const float* core_W  = (const float*)d_in[6];
    const float* core_b  = (const float*)d_in[7];
    const float* core_g  = (const float*)d_in[8];
    const float* core_bt = (const float*)d_in[9];
    const float* ctx_W   = (const float*)d_in[10];
    const float* ctx_b   = (const float*)d_in[11];
    const float* ctx_g   = (const float*)d_in[12];
    const float* ctx_bt  = (const float*)d_in[13];
    const float* att_W1  = (const float*)d_in[14];
    const float* att_b1  = (const float*)d_in[15];
    const float* att_g   = (const float*)d_in[16];
    const float* att_bt  = (const float*)d_in[17];
    const float* att_W2  = (const float*)d_in[18];
    const float* att_b2  = (const float*)d_in[19];
    const float* out_W   = (const float*)d_in[20];
    const float* out_b   = (const float*)d_in[21];
    float* out = (float*)d_out;

    static int configured = 0;
    const int pair_smB = (5 * KK * HP + 2 * NP * HP + NP * HA_ + NP + 4 * NP) * (int)sizeof(float);
    if (!configured) {
        cudaFuncSetAttribute(pair_kernel, cudaFuncAttributeMaxDynamicSharedMemorySize, pair_smB);
        configured = 1;
    }

    pack_all<<<(N_TOT + 255) / 256, 256>>>(enc_W, core_W, ctx_W, att_W1, core_g);
    tvec_kernel<<<2, 256>>>(ctx_W, ctx_b, att_W1, att_b1, core_g, core_bt);
    wpad_kernel<<<(KP * NPAD2 + 255) / 256, 256>>>(out_W);
    enc_kernel<<<BK / ER, 256>>>(state, enc_b, enc_g, enc_bt);
    pair_kernel<<<NB, 512, pair_smB>>>(core_b, ctx_g, ctx_bt,
                                       att_g, att_bt, att_W2, att_b2);
    concat_kernel<<<(int)(((size_t)BK * (KP / 4) + 255) / 256), 256>>>(x);
    out_mma_kernel<<<BK / 64, 256>>>(out_b, out);
}

// round 15
// speedup vs baseline: 1.8381x; 1.8381x over previous
#include <cuda_runtime.h>
#include <math.h>

#define KK   8
#define H    250
#define HP   252
#define NP   56
#define HA_  100
#define MM   576
#define NB   2048
#define BK   (NB*KK)
#define CIN  1076
#define EPS_ 1e-5f
#define K2E  125
#define K2C  250
#define KP   1080
#define NPAD2 256

typedef unsigned long long u64t;

__device__ __forceinline__ u64t pack2(float lo, float hi) {
    u64t r;
    asm("mov.b64 %0, {%1, %2};" : "=l"(r) : "f"(lo), "f"(hi));
    return r;
}
__device__ __forceinline__ void fma2(u64t& d, u64t a, u64t b) {
    asm("fma.rn.f32x2 %0, %1, %2, %0;" : "+l"(d) : "l"(a), "l"(b));
}
__device__ __forceinline__ float sum2(u64t v) {
    float lo, hi;
    asm("mov.b64 {%0, %1}, %2;" : "=f"(lo), "=f"(hi) : "l"(v));
    return lo + hi;
}
__device__ __forceinline__ float tf32r(float f) {
    unsigned u;
    asm("cvt.rna.tf32.f32 %0, %1;" : "=r"(u) : "f"(f));
    return __uint_as_float(u);
}

#define MMA_TF32(D, A, B0, B1) \
    asm volatile("mma.sync.aligned.m16n8k8.row.col.f32.tf32.tf32.f32 " \
        "{%0,%1,%2,%3}, {%4,%5,%6,%7}, {%8,%9}, {%0,%1,%2,%3};" \
        : "+f"((D)[0]), "+f"((D)[1]), "+f"((D)[2]), "+f"((D)[3]) \
        : "r"((A)[0]), "r"((A)[1]), "r"((A)[2]), "r"((A)[3]), "r"(B0), "r"(B1))

// scratch + packed weights (allocation-free rule: device globals)
__device__ float g_s1 [(size_t)BK * H];
__device__ float g_eff[(size_t)BK * H];
__device__ u64t  g_Wenc [K2E * H];
__device__ u64t  g_Wcore[K2C * H];
__device__ u64t  g_Wctx [K2E * H];      // pre-multiplied by core_g (LN fold)
__device__ u64t  g_Watt [K2E * HA_];    // pre-multiplied by core_g (LN fold)
__device__ float g_t1c[H],  g_t2c[H];
__device__ float g_t1a[HA_], g_t2a[HA_];
// mma weight hi/lo planes (B side only; A converted in-kernel)
__device__ float g_WHp [KP * NPAD2];
__device__ float g_WLp [KP * NPAD2];

// ---------------------------------------------------------------------------
// pack kernel
// ---------------------------------------------------------------------------
#define N_E (K2E*H)
#define N_C (K2C*H)
#define N_A (K2E*HA_)
#define N_TOT (N_E + N_C + N_E + N_A)
__global__ void pack_all(const float* __restrict__ encW, const float* __restrict__ coreW,
                         const float* __restrict__ ctxW, const float* __restrict__ attW,
                         const float* __restrict__ core_g) {
    int i = blockIdx.x * 256 + threadIdx.x;
    if (i < N_E) {
        int k2 = i / H, c = i - k2 * H;
        g_Wenc[i] = pack2(encW[(2 * k2) * H + c], encW[(2 * k2 + 1) * H + c]);
        return;
    }
    i -= N_E;
    if (i < N_C) {
        int k2 = i / H, c = i - k2 * H;
        g_Wcore[i] = pack2(coreW[(2 * k2) * H + c], coreW[(2 * k2 + 1) * H + c]);
        return;
    }
    i -= N_C;
    if (i < N_E) {
        int k2 = i / H, c = i - k2 * H;
        g_Wctx[i] = pack2(core_g[2 * k2]     * ctxW[(2 * k2) * H + c],
                          core_g[2 * k2 + 1] * ctxW[(2 * k2 + 1) * H + c]);
        return;
    }
    i -= N_E;
    if (i < N_A) {
        int k2 = i / HA_, c = i - k2 * HA_;
        g_Watt[i] = pack2(core_g[2 * k2]     * attW[(2 * k2) * HA_ + c],
                          core_g[2 * k2 + 1] * attW[(2 * k2 + 1) * HA_ + c]);
    }
}

// ---------------------------------------------------------------------------
// t-vector kernel
// ---------------------------------------------------------------------------
__global__ void tvec_kernel(const float* __restrict__ ctxW, const float* __restrict__ ctx_b,
                            const float* __restrict__ attW, const float* __restrict__ att_b1,
                            const float* __restrict__ core_g, const float* __restrict__ core_bt) {
    int n = blockIdx.x * 256 + threadIdx.x;
    if (n < H) {
        float t1 = 0.f, t2 = 0.f;
        #pragma unroll 4
        for (int c = 0; c < H; c++) {
            float w = ctxW[(size_t)c * H + n];
            t1 += w * core_bt[c];
            t2 += w * core_g[c];
        }
        g_t1c[n] = t1 + ctx_b[n];
        g_t2c[n] = t2;
    } else if (n < H + HA_) {
        int m = n - H;
        float t1 = 0.f, t2 = 0.f;
        #pragma unroll 4
        for (int c = 0; c < H; c++) {
            float w = attW[(size_t)c * HA_ + m];
            t1 += w * core_bt[c];
            t2 += w * core_g[c];
        }
        g_t1a[m] = t1 + att_b1[m];
        g_t2a[m] = t2;
    }
}

// ---------------------------------------------------------------------------
// out_W pad + tf32 hi/lo split
// ---------------------------------------------------------------------------
__global__ void wpad_kernel(const float* __restrict__ W) {
    int i = blockIdx.x * 256 + threadIdx.x;
    if (i >= KP * NPAD2) return;
    int k = i / NPAD2, n = i - k * NPAD2;
    float v = (k < CIN && n < H) ? W[(size_t)k * H + n] : 0.f;
    float hi = tf32r(v);
    g_WHp[i] = hi;
    g_WLp[i] = tf32r(v - hi);
}

// ---------------------------------------------------------------------------
// shared FFMA2 GEMM helpers
// ---------------------------------------------------------------------------
template<int NR>
__device__ __forceinline__ void chunk_body(
    u64t* a0, u64t* a1, const float* base, int rowstride, int k,
    const u64t* wa0, const u64t* wa1)
{
    #pragma unroll
    for (int e = 0; e < NR; e++) {
        ulonglong2 v0 = *(const ulonglong2*)&base[e * rowstride + k];
        ulonglong2 v1 = *(const ulonglong2*)&base[e * rowstride + k + 4];
        fma2(a0[e], v0.x, wa0[0]); fma2(a0[e], v0.y, wa0[1]);
        fma2(a0[e], v1.x, wa0[2]); fma2(a0[e], v1.y, wa0[3]);
        fma2(a1[e], v0.x, wa1[0]); fma2(a1[e], v0.y, wa1[1]);
        fma2(a1[e], v1.x, wa1[2]); fma2(a1[e], v1.y, wa1[3]);
    }
}
__device__ __forceinline__ void ldw4(u64t* w0, u64t* w1,
                                     const u64t* W0, const u64t* W1,
                                     int k2, int stride) {
    #pragma unroll
    for (int j = 0; j < 4; j++) {
        w0[j] = W0[(size_t)(k2 + j) * stride];
        w1[j] = W1[(size_t)(k2 + j) * stride];
    }
}
__device__ __forceinline__ void cpw4(u64t* wa0, u64t* wa1,
                                     const u64t* wb0, const u64t* wb1) {
    #pragma unroll
    for (int j = 0; j < 4; j++) { wa0[j] = wb0[j]; wa1[j] = wb1[j]; }
}

// ---------------------------------------------------------------------------
// Kernel 1: s1 = LN(relu(state @ enc_W + enc_b)); (R13 verbatim)
// ---------------------------------------------------------------------------
#define ER 16
__global__ __launch_bounds__(256, 2) void enc_kernel(
    const float* __restrict__ state, const float* __restrict__ b,
    const float* __restrict__ g, const float* __restrict__ bt)
{
    __shared__ float sst[ER * HP];
    __shared__ float st[ER * 2];

    const int t = threadIdx.x;
    const size_t base = (size_t)blockIdx.x * ER;
    const float* srow = state + base * H;

    for (int i = t; i < ER * H; i += 256) {
        int r = i / H, c = i - r * H;
        sst[r * HP + c] = srow[i];
    }
    __syncthreads();

    const int h = t >> 7, u = t & 127;
    const int c0 = u, c1 = u + 128;
    const int c1ok = (c1 < H);
    const int c1v = c1ok ? c1 : 0;

    float relu0[8], relu1[8];
    {
        const u64t* W0 = g_Wenc + c0;
        const u64t* W1 = g_Wenc + c1v;
        const float* sr = sst + h * 8 * HP;
        u64t a0[8], a1[8];
        #pragma unroll
        for (int e = 0; e < 8; e++) { a0[e] = 0ull; a1[e] = 0ull; }

        u64t wa0[4], wa1[4];
        ldw4(wa0, wa1, W0, W1, 0, H);
        #pragma unroll 2
        for (int kc = 0; kc < 120; kc += 4) {
            u64t wb0[4], wb1[4];
            ldw4(wb0, wb1, W0, W1, kc + 4, H);
            chunk_body<8>(a0, a1, sr, HP, 2 * kc, wa0, wa1);
            cpw4(wa0, wa1, wb0, wb1);
        }
        chunk_body<8>(a0, a1, sr, HP, 240, wa0, wa1);
        {
            u64t wt0 = W0[(size_t)124 * H], wt1 = W1[(size_t)124 * H];
            #pragma unroll
            for (int e = 0; e < 8; e++) {
                u64t v = *(const u64t*)&sr[e * HP + 248];
                fma2(a0[e], v, wt0);
                fma2(a1[e], v, wt1);
            }
        }
        float b0 = b[c0], b1 = b[c1v];
        #pragma unroll
        for (int e = 0; e < 8; e++) {
            relu0[e] = fmaxf(sum2(a0[e]) + b0, 0.f);
            relu1[e] = fmaxf(sum2(a1[e]) + b1, 0.f);
        }
    }
    __syncthreads();
    #pragma unroll
    for (int e = 0; e < 8; e++) {
        sst[(8 * h + e) * HP + c0] = relu0[e];
        if (c1ok) sst[(8 * h + e) * HP + c1] = relu1[e];
    }
    __syncthreads();

    const int warp = t >> 5, lane = t & 31;
    for (int r = warp; r < ER; r += 8) {
        float s = 0.f, s2 = 0.f;
        for (int k = lane; k < H; k += 32) {
            float v = sst[r * HP + k];
            s += v; s2 += v * v;
        }
        #pragma unroll
        for (int off = 16; off; off >>= 1) {
            s  += __shfl_xor_sync(0xffffffffu, s,  off);
            s2 += __shfl_xor_sync(0xffffffffu, s2, off);
        }
        if (lane == 0) {
            float mu = s * (1.f / H);
            st[r * 2]     = mu;
            st[r * 2 + 1] = rsqrtf(s2 * (1.f / H) - mu * mu + EPS_);
        }
    }
    __syncthreads();

    {
        float g0 = g[c0], bb0 = bt[c0];
        float g1 = g[c1v], bb1 = bt[c1v];
        #pragma unroll
        for (int e = 0; e < 8; e++) {
            int r = 8 * h + e;
            g_s1[(base + r) * H + c0] = (relu0[e] - st[r * 2]) * st[r * 2 + 1] * g0 + bb0;
            if (c1ok)
                g_s1[(base + r) * H + c1] = (relu1[e] - st[r * 2]) * st[r * 2 + 1] * g1 + bb1;
        }
    }
}

// ---------------------------------------------------------------------------
// Kernel 2: fused pair pipeline (R13 verbatim — known-good 1151 µs config)
// ---------------------------------------------------------------------------
__global__ __launch_bounds__(512, 1) void pair_kernel(
    const float* __restrict__ core_b,
    const float* __restrict__ ctx_g,  const float* __restrict__ ctx_bt,
    const float* __restrict__ att_g,  const float* __restrict__ att_bt,
    const float* __restrict__ att_W2, const float* __restrict__ att_b2)
{
    extern __shared__ float sm[];
    float* s1s   = sm;                    // 8  * HP
    float* fbufA = s1s   + KK * HP;
    float* fbufB = fbufA + KK * HP;
    float* obufA = fbufB + KK * HP;
    float* obufB = obufA + KK * HP;
    float* coreb = obufB + KK * HP;       // 56 * HP (raw, post-relu)
    float* ctxb  = coreb + NP * HP;       // 56 * HP (raw, post-relu)
    float* attb  = ctxb  + NP * HP;       // 56 * HA_
    float* attv  = attb  + NP * HA_;      // 56
    float* stA   = attv  + NP;            // 56*2  (mu*rs, rs) of coreb
    float* stC   = stA   + NP * 2;        // 56*2  (mu*rs, rs) of ctxb

    const int t = threadIdx.x;
    const int grp = blockIdx.x;
    const int warp = t >> 5, lane = t & 31;

    const int qg = t >> 7, u = t & 127;
    const int c0 = u, c1 = u + 128;
    const int c1ok = (c1 < H);
    const int c1v = c1ok ? c1 : 0;

    for (int i = t; i < KK * H; i += 512) {
        int r = i / H, c = i - r * H;
        s1s[r * HP + c] = g_s1[((size_t)grp * KK + r) * H + c];
    }
    __syncthreads();

    // ---- core GEMM: quadrant = (k-half, focal/other); 2 cols per thread ----
    {
        const int wh = qg & 1;
        const int kh = qg >> 1;
        const u64t* W0 = g_Wcore + (size_t)(wh * 125) * H + c0;
        const u64t* W1 = g_Wcore + (size_t)(wh * 125) * H + c1v;
        u64t a0[8], a1[8];
        #pragma unroll
        for (int e = 0; e < 8; e++) { a0[e] = 0ull; a1[e] = 0ull; }

        int kc = kh ? 64 : 0;
        const int kstop = kh ? 120 : 60;
        u64t wa0[4], wa1[4];
        ldw4(wa0, wa1, W0, W1, kc, H);
        #pragma unroll 1
        for (; kc < kstop; kc += 4) {
            u64t wb0[4], wb1[4];
            ldw4(wb0, wb1, W0, W1, kc + 4, H);
            chunk_body<8>(a0, a1, s1s, HP, 2 * kc, wa0, wa1);
            cpw4(wa0, wa1, wb0, wb1);
        }
        chunk_body<8>(a0, a1, s1s, HP, 2 * kstop, wa0, wa1);
        if (kh) {
            u64t wt0 = W0[(size_t)124 * H], wt1 = W1[(size_t)124 * H];
            #pragma unroll
            for (int e = 0; e < 8; e++) {
                u64t v = *(const u64t*)&s1s[e * HP + 248];
                fma2(a0[e], v, wt0);
                fma2(a1[e], v, wt1);
            }
        }
        float* fd = kh ? (wh ? obufB : fbufB) : (wh ? obufA : fbufA);
        #pragma unroll
        for (int e = 0; e < 8; e++) {
            fd[e * HP + c0] = sum2(a0[e]);
            if (c1ok) fd[e * HP + c1] = sum2(a1[e]);
        }
    }
    __syncthreads();

    // ---- merged assemble + LN stats (warp per pair; division-free) ----
    for (int p = warp; p < NP; p += 16) {
        const int fi = (p * 9363) >> 16;        // p / 7
        const int jj = p - fi * 7;
        const int o = jj + (jj >= fi);
        const float* fA = fbufA + fi * HP;
        const float* fB = fbufB + fi * HP;
        const float* oA = obufA + o * HP;
        const float* oB = obufB + o * HP;
        float s = 0.f, s2 = 0.f;
        for (int c = lane; c < H; c += 32) {
            float v = fmaxf(fA[c] + fB[c] + oA[c] + oB[c] + core_b[c], 0.f);
            coreb[p * HP + c] = v;
            s += v; s2 += v * v;
        }
        #pragma unroll
        for (int off = 16; off; off >>= 1) {
            s  += __shfl_xor_sync(0xffffffffu, s,  off);
            s2 += __shfl_xor_sync(0xffffffffu, s2, off);
        }
        if (lane == 0) {
            float mu = s * (1.f / H);
            float rs = rsqrtf(s2 * (1.f / H) - mu * mu + EPS_);
            stA[2 * p]     = mu * rs;
            stA[2 * p + 1] = rs;
        }
    }
    __syncthreads();

    // ---- ctx GEMM over RAW coreb with folded weights; LN in epilogue ----
    {
        const int pbase = qg * 14;
        const u64t* W0 = g_Wctx + c0;
        const u64t* W1 = g_Wctx + c1v;
        u64t a0[14], a1[14];
        #pragma unroll
        for (int pp = 0; pp < 14; pp++) { a0[pp] = 0ull; a1[pp] = 0ull; }

        u64t wa0[2], wa1[2];
        wa0[0] = W0[0]; wa0[1] = W0[H];
        wa1[0] = W1[0]; wa1[1] = W1[H];
        #pragma unroll 2
        for (int kc2 = 0; kc2 < 122; kc2 += 2) {
            u64t wb0[2], wb1[2];
            wb0[0] = W0[(size_t)(kc2 + 2) * H]; wb0[1] = W0[(size_t)(kc2 + 3) * H];
            wb1[0] = W1[(size_t)(kc2 + 2) * H]; wb1[1] = W1[(size_t)(kc2 + 3) * H];
            const int k = 2 * kc2;
            #pragma unroll
            for (int pp = 0; pp < 14; pp++) {
                ulonglong2 v = *(const ulonglong2*)&coreb[(pbase + pp) * HP + k];
                fma2(a0[pp], v.x, wa0[0]); fma2(a0[pp], v.y, wa0[1]);
                fma2(a1[pp], v.x, wa1[0]); fma2(a1[pp], v.y, wa1[1]);
            }
            wa0[0] = wb0[0]; wa0[1] = wb0[1];
            wa1[0] = wb1[0]; wa1[1] = wb1[1];
        }
        {
            #pragma unroll
            for (int pp = 0; pp < 14; pp++) {
                ulonglong2 v = *(const ulonglong2*)&coreb[(pbase + pp) * HP + 244];
                fma2(a0[pp], v.x, wa0[0]); fma2(a0[pp], v.y, wa0[1]);
                fma2(a1[pp], v.x, wa1[0]); fma2(a1[pp], v.y, wa1[1]);
            }
        }
        {
            u64t wt0 = W0[(size_t)124 * H], wt1 = W1[(size_t)124 * H];
            #pragma unroll
            for (int pp = 0; pp < 14; pp++) {
                u64t v = *(const u64t*)&coreb[(pbase + pp) * HP + 248];
                fma2(a0[pp], v, wt0);
                fma2(a1[pp], v, wt1);
            }
        }
        const float t10 = g_t1c[c0], t20 = g_t2c[c0];
        const float t11 = g_t1c[c1v], t21 = g_t2c[c1v];
        #pragma unroll
        for (int pp = 0; pp < 14; pp++) {
            const int p = pbase + pp;
            const float ms = stA[2 * p], rs = stA[2 * p + 1];
            ctxb[p * HP + c0] = fmaxf(rs * sum2(a0[pp]) - ms * t20 + t10, 0.f);
            if (c1ok)
                ctxb[p * HP + c1] = fmaxf(rs * sum2(a1[pp]) - ms * t21 + t11, 0.f);
        }
    }

    // ---- att1 GEMM over RAW coreb (folded); 8 groups x 7 pairs x 2 cols ----
    {
        const int g8 = t >> 6, u6 = t & 63;
        if (u6 < 50) {
            const int pbase = g8 * 7;
            const int ac0 = u6, ac1 = u6 + 50;
            const u64t* W0 = g_Watt + ac0;
            const u64t* W1 = g_Watt + ac1;
            u64t a0[7], a1[7];
            #pragma unroll
            for (int pp = 0; pp < 7; pp++) { a0[pp] = 0ull; a1[pp] = 0ull; }

            u64t wa0[4], wa1[4];
            ldw4(wa0, wa1, W0, W1, 0, HA_);
            #pragma unroll 2
            for (int kc = 0; kc < 120; kc += 4) {
                u64t wb0[4], wb1[4];
                ldw4(wb0, wb1, W0, W1, kc + 4, HA_);
                chunk_body<7>(a0, a1, coreb + pbase * HP, HP, 2 * kc, wa0, wa1);
                cpw4(wa0, wa1, wb0, wb1);
            }
            chunk_body<7>(a0, a1, coreb + pbase * HP, HP, 240, wa0, wa1);
            {
                u64t wt0 = W0[(size_t)124 * HA_], wt1 = W1[(size_t)124 * HA_];
                #pragma unroll
                for (int pp = 0; pp < 7; pp++) {
                    u64t v = *(const u64t*)&coreb[(pbase + pp) * HP + 248];
                    fma2(a0[pp], v, wt0);
                    fma2(a1[pp], v, wt1);
                }
            }
            const float t10 = g_t1a[ac0], t20 = g_t2a[ac0];
            const float t11 = g_t1a[ac1], t21 = g_t2a[ac1];
            #pragma unroll
            for (int pp = 0; pp < 7; pp++) {
                const int p = pbase + pp;
                const float ms = stA[2 * p], rs = stA[2 * p + 1];
                attb[p * HA_ + ac0] = tanhf(rs * sum2(a0[pp]) - ms * t20 + t10);
                attb[p * HA_ + ac1] = tanhf(rs * sum2(a1[pp]) - ms * t21 + t11);
            }
        }
    }
    __syncthreads();

    // ---- ctx LN stats + att LN + att2 + sigmoid (warp per pair) ----
    for (int p = warp; p < NP; p += 16) {
        {
            float s = 0.f, s2 = 0.f;
            for (int k = lane; k < H; k += 32) {
                float v = ctxb[p * HP + k];
                s += v; s2 += v * v;
            }
            #pragma unroll
            for (int off = 16; off; off >>= 1) {
                s  += __shfl_xor_sync(0xffffffffu, s,  off);
                s2 += __shfl_xor_sync(0xffffffffu, s2, off);
            }
            if (lane == 0) {
                float mu = s * (1.f / H);
                float rs = rsqrtf(s2 * (1.f / H) - mu * mu + EPS_);
                stC[2 * p]     = mu * rs;
                stC[2 * p + 1] = rs;
            }
        }
        {
            float s = 0.f, s2 = 0.f;
            for (int k = lane; k < HA_; k += 32) {
                float v = attb[p * HA_ + k];
                s += v; s2 += v * v;
            }
            #pragma unroll
            for (int off = 16; off; off >>= 1) {
                s  += __shfl_xor_sync(0xffffffffu, s,  off);
                s2 += __shfl_xor_sync(0xffffffffu, s2, off);
            }
            float mu = s * (1.f / HA_);
            float rs = rsqrtf(s2 * (1.f / HA_) - mu * mu + EPS_);
            float s3 = 0.f;
            for (int k = lane; k < HA_; k += 32) {
                float v = (attb[p * HA_ + k] - mu) * rs * att_g[k] + att_bt[k];
                s3 += v * att_W2[k];
            }
            #pragma unroll
            for (int off = 16; off; off >>= 1)
                s3 += __shfl_xor_sync(0xffffffffu, s3, off);
            if (lane == 0)
                attv[p] = 1.f / (1.f + expf(-(s3 + att_b2[0])));
        }
    }
    __syncthreads();

    // ---- effect (folded ctx-LN) ----
    {
        const int c = t & 255, eh = t >> 8;
        if (c < H) {
            const float cgc = ctx_g[c], cbtc = ctx_bt[c];
            #pragma unroll
            for (int e4 = 0; e4 < 4; e4++) {
                const int e = eh * 4 + e4;
                float acc = 0.f, A = 0.f, Bs = 0.f;
                #pragma unroll
                for (int j = 0; j < 7; j++) {
                    const int p = e * 7 + j;
                    const float av = attv[p];
                    const float w  = av * stC[2 * p + 1];
                    acc += w * ctxb[p * HP + c];
                    A   += av;
                    Bs  += av * stC[2 * p];
                }
                g_eff[((size_t)grp * KK + e) * H + c] = cgc * (acc - Bs) + A * cbtc;
            }
        }
    }
}

// ---------------------------------------------------------------------------
// Kernel 3: out GEMM via tf32 mma.sync (3xTF32), concat FUSED into A-load.
// ---------------------------------------------------------------------------
__device__ __forceinline__ float load_tot(const float* __restrict__ x, int row, int k) {
    if (k < H)          return g_s1[(size_t)row * H + k];
    if (k < 2 * H)      return g_eff[(size_t)row * H + (k - H)];
    if (k < CIN)        return x[(size_t)row * MM + (k - 2 * H)];
    return 0.f;
}

#define LOAD_STAGE(s, k0) do {                                                        \
    {   /* A: gather [s1|eff|x] + tf32 hi/lo split in-register */                     \
        const int row = m0 + am;                                                      \
        float v0 = load_tot(x, row, (k0) + ak);                                       \
        float v1 = load_tot(x, row, (k0) + ak + 1);                                   \
        float h0 = tf32r(v0), h1 = tf32r(v1);                                         \
        AsH[s][am * 8 + ak]     = h0;                                                 \
        AsH[s][am * 8 + ak + 1] = h1;                                                 \
        AsL[s][am * 8 + ak]     = tf32r(v0 - h0);                                     \
        AsL[s][am * 8 + ak + 1] = tf32r(v1 - h1);                                     \
    }                                                                                 \
    {   /* B: precomputed hi/lo planes */                                             \
        const float* wh = &g_WHp[(size_t)((k0) + bk) * NPAD2 + bn];                   \
        const float* wl = &g_WLp[(size_t)((k0) + bk) * NPAD2 + bn];                   \
        *(float4*)&BsH[s][bk * 260 + bn]     = *(const float4*)wh;                    \
        *(float4*)&BsH[s][bk * 260 + bn + 4] = *(const float4*)(wh + 4);              \
        *(float4*)&BsL[s][bk * 260 + bn]     = *(const float4*)wl;                    \
        *(float4*)&BsL[s][bk * 260 + bn + 4] = *(const float4*)(wl + 4);              \
    }                                                                                 \
} while (0)

__global__ __launch_bounds__(256, 2) void out_mma_kernel(
    const float* __restrict__ x,
    const float* __restrict__ bias, float* __restrict__ out)
{
    __shared__ float AsH[2][64 * 8], AsL[2][64 * 8];
    __shared__ float BsH[2][8 * 260], BsL[2][8 * 260];

    const int t = threadIdx.x;
    const int m0 = blockIdx.x * 64;
    const int w = t >> 5, lane = t & 31;
    const int wm = w & 1, wn = w >> 1;
    const int gid = lane >> 2, ctid = lane & 3;

    const int am = t >> 2;              // A row 0..63
    const int ak = (t & 3) * 2;         // A k-pair within 8
    const int bk = t >> 5;              // B k row 0..7
    const int bn = (t & 31) * 8;        // B n 0..248

    float d[2][8][4];
    #pragma unroll
    for (int mf = 0; mf < 2; mf++)
        #pragma unroll
        for (int nf = 0; nf < 8; nf++)
            #pragma unroll
            for (int q = 0; q < 4; q++) d[mf][nf][q] = 0.f;

    LOAD_STAGE(0, 0);

    #pragma unroll 1
    for (int ks = 0; ks < 135; ks++) {
        const int s = ks & 1;
        __syncthreads();
        if (ks + 1 < 135) LOAD_STAGE(s ^ 1, (ks + 1) * 8);

        unsigned aH[2][4], aL[2][4];
        #pragma unroll
        for (int mf = 0; mf < 2; mf++) {
            const int rb = wm * 32 + mf * 16;
            aH[mf][0] = __float_as_uint(AsH[s][(rb + gid) * 8 + ctid]);
            aH[mf][1] = __float_as_uint(AsH[s][(rb + gid + 8) * 8 + ctid]);
            aH[mf][2] = __float_as_uint(AsH[s][(rb + gid) * 8 + ctid + 4]);
            aH[mf][3] = __float_as_uint(AsH[s][(rb + gid + 8) * 8 + ctid + 4]);
            aL[mf][0] = __float_as_uint(AsL[s][(rb + gid) * 8 + ctid]);
            aL[mf][1] = __float_as_uint(AsL[s][(rb + gid + 8) * 8 + ctid]);
            aL[mf][2] = __float_as_uint(AsL[s][(rb + gid) * 8 + ctid + 4]);
            aL[mf][3] = __float_as_uint(AsL[s][(rb + gid + 8) * 8 + ctid + 4]);
        }
        #pragma unroll
        for (int nf = 0; nf < 8; nf++) {
            const int n = wn * 64 + nf * 8 + gid;
            unsigned bH0 = __float_as_uint(BsH[s][ctid * 260 + n]);
            unsigned bH1 = __float_as_uint(BsH[s][(ctid + 4) * 260 + n]);
            unsigned bL0 = __float_as_uint(BsL[s][ctid * 260 + n]);
            unsigned bL1 = __float_as_uint(BsL[s][(ctid + 4) * 260 + n]);
            #pragma unroll
            for (int mf = 0; mf < 2; mf++) {
                MMA_TF32(d[mf][nf], aH[mf], bH0, bH1);
                MMA_TF32(d[mf][nf], aL[mf], bH0, bH1);
                MMA_TF32(d[mf][nf], aH[mf], bL0, bL1);
            }
        }
    }

    #pragma unroll
    for (int mf = 0; mf < 2; mf++) {
        const int r0 = m0 + wm * 32 + mf * 16 + gid;
        #pragma unroll
        for (int nf = 0; nf < 8; nf++) {
            const int n = wn * 64 + nf * 8 + 2 * ctid;
            if (n < H) {
                float b0 = bias[n], b1 = bias[n + 1];
                out[(size_t)r0 * H + n]           = d[mf][nf][0] + b0;
                out[(size_t)r0 * H + n + 1]       = d[mf][nf][1] + b1;
                out[(size_t)(r0 + 8) * H + n]     = d[mf][nf][2] + b0;
                out[(size_t)(r0 + 8) * H + n + 1] = d[mf][nf][3] + b1;
            }
        }
    }
}

// ---------------------------------------------------------------------------
extern "C" void kernel_launch(void* const* d_in, const int* in_sizes, int n_in,
                              void* d_out, int out_size)
{
    const float* x       = (const float*)d_in[0];
    const float* state   = (const float*)d_in[1];
    const float* enc_W   = (const float*)d_in[2];
    const float* enc_b   = (const float*)d_in[3];
    const float* enc_g   = (const float*)d_in[4];
    const float* enc_bt  = (const float*)d_in[5];
    const float* core_W  = (const float*)d_in[6];
    const float* core_b  = (const float*)d_in[7];
    const float* core_g  = (const float*)d_in[8];
    const float* core_bt = (const float*)d_in[9];
    const float* ctx_W   = (const float*)d_in[10];
    const float* ctx_b   = (const float*)d_in[11];
    const float* ctx_g   = (const float*)d_in[12];
    const float* ctx_bt  = (const float*)d_in[13];
    const float* att_W1  = (const float*)d_in[14];
    const float* att_b1  = (const float*)d_in[15];
    const float* att_g   = (const float*)d_in[16];
    const float* att_bt  = (const float*)d_in[17];
    const float* att_W2  = (const float*)d_in[18];
    const float* att_b2  = (const float*)d_in[19];
    const float* out_W   = (const float*)d_in[20];
    const float* out_b   = (const float*)d_in[21];
    float* out = (float*)d_out;

    static int configured = 0;
    const int pair_smB = (5 * KK * HP + 2 * NP * HP + NP * HA_ + NP + 4 * NP) * (int)sizeof(float);
    if (!configured) {
        cudaFuncSetAttribute(pair_kernel, cudaFuncAttributeMaxDynamicSharedMemorySize, pair_smB);
        configured = 1;
    }

    pack_all<<<(N_TOT + 255) / 256, 256>>>(enc_W, core_W, ctx_W, att_W1, core_g);
    tvec_kernel<<<2, 256>>>(ctx_W, ctx_b, att_W1, att_b1, core_g, core_bt);
    wpad_kernel<<<(KP * NPAD2 + 255) / 256, 256>>>(out_W);
    enc_kernel<<<BK / ER, 256>>>(state, enc_b, enc_g, enc_bt);
    pair_kernel<<<NB, 512, pair_smB>>>(core_b, ctx_g, ctx_bt,
                                       att_g, att_bt, att_W2, att_b2);
    out_mma_kernel<<<BK / 64, 256>>>(x, out_b, out);
}